// round 3
// baseline (speedup 1.0000x reference)
#include <cuda_runtime.h>
#include <cuda_bf16.h>
#include <math.h>

// ---------------------------------------------------------------------------
// Problem constants
// ---------------------------------------------------------------------------
#define SEQ      4096
#define DIM      2048
#define NH       16
#define NKV      4
#define HD       128
#define KVDIM    (NKV*HD)          // 512
#define QKVN     (DIM + 2*KVDIM)   // 3072
#define NROWS_W  (QKVN + DIM)      // 5120 quantize rows

// ---------------------------------------------------------------------------
// Device-global scratch (no cudaMalloc allowed)
// ---------------------------------------------------------------------------
__device__ float g_Wqkv[QKVN * DIM];     // quantized [q|k|v] weights, row-major [3072][2048]
__device__ float g_Wp  [DIM  * DIM];     // quantized output-proj weights  [2048][2048]
__device__ float g_QKV [SEQ  * QKVN];    // x @ Wqkv^T : [4096][3072] = [q 2048 | k 512 | v 512]
__device__ float g_Y   [SEQ  * DIM];     // attention output [4096][2048] (pos, h*128+d)
__device__ float g_cos [SEQ * (HD/2)];   // RoPE tables [4096][64]
__device__ float g_sin [SEQ * (HD/2)];

// ---------------------------------------------------------------------------
// 1) RoPE tables in double precision (avoids fp32 large-angle phase error and
//    --use_fast_math __sinf inaccuracy)
// ---------------------------------------------------------------------------
__global__ void rope_table_kernel() {
    int idx = blockIdx.x * blockDim.x + threadIdx.x;
    if (idx >= SEQ * (HD/2)) return;
    int t = idx >> 6;
    int j = idx & 63;
    double invf = pow(10000.0, -(double)j / 64.0);
    double ang  = (double)t * invf;
    double sn, cn;
    sincos(ang, &sn, &cn);
    g_cos[idx] = (float)cn;
    g_sin[idx] = (float)sn;
}

// ---------------------------------------------------------------------------
// 2) BitLinear weight quantization: per row s = max(mean|W|,1e-5),
//    w_eff = clip(rint(W/s),-1,1)*s.  One 256-thread block per row.
//    Rows: [0,2048) wq -> g_Wqkv ; [2048,2560) wk ; [2560,3072) wv ;
//          [3072,5120) wp -> g_Wp
// ---------------------------------------------------------------------------
__global__ __launch_bounds__(256) void quantize_kernel(
    const float* __restrict__ wq, const float* __restrict__ wk,
    const float* __restrict__ wv, const float* __restrict__ wp)
{
    int row = blockIdx.x;
    const float* src; float* dst;
    if      (row < DIM)        { src = wq + (size_t)row * DIM;          dst = g_Wqkv + (size_t)row * DIM; }
    else if (row < DIM + KVDIM){ src = wk + (size_t)(row - DIM) * DIM;  dst = g_Wqkv + (size_t)row * DIM; }
    else if (row < QKVN)       { src = wv + (size_t)(row - DIM - KVDIM) * DIM; dst = g_Wqkv + (size_t)row * DIM; }
    else                       { src = wp + (size_t)(row - QKVN) * DIM; dst = g_Wp + (size_t)(row - QKVN) * DIM; }

    __shared__ double red[256];
    double acc = 0.0;
    for (int k = threadIdx.x; k < DIM; k += 256) acc += (double)fabsf(src[k]);
    red[threadIdx.x] = acc;
    __syncthreads();
    for (int off = 128; off > 0; off >>= 1) {
        if (threadIdx.x < off) red[threadIdx.x] += red[threadIdx.x + off];
        __syncthreads();
    }
    float s = fmaxf((float)(red[0] / (double)DIM), 1e-5f);
    for (int k = threadIdx.x; k < DIM; k += 256) {
        float w = rintf(src[k] / s);           // round-half-even, matches jnp.round
        w = fminf(fmaxf(w, -1.f), 1.f);
        dst[k] = w * s;
    }
}

// ---------------------------------------------------------------------------
// 3) GEMM: C[M,N] = A[M,K(row-major)] @ B[N,K(row-major)]^T
//    128x128 tiles, BK=16, 8x8 per thread, 256 threads.
// ---------------------------------------------------------------------------
__device__ __forceinline__ void gemm_body(
    const float* __restrict__ A, const float* __restrict__ B,
    float* __restrict__ C, int N, int K)
{
    __shared__ float As[16][132];
    __shared__ float Bs[16][132];
    int tid  = threadIdx.x;
    int trow = tid >> 4;       // 0..15
    int tcol = tid & 15;       // 0..15
    const float* Ab = A + (size_t)blockIdx.y * 128 * K;
    const float* Bb = B + (size_t)blockIdx.x * 128 * K;

    float acc[8][8];
    #pragma unroll
    for (int r = 0; r < 8; r++)
        #pragma unroll
        for (int c = 0; c < 8; c++) acc[r][c] = 0.f;

    for (int k0 = 0; k0 < K; k0 += 16) {
        #pragma unroll
        for (int i = 0; i < 2; i++) {
            int l   = tid + i * 256;           // 0..511
            int row = l >> 2;
            int k4  = (l & 3) * 4;
            float4 v = *(const float4*)(Ab + (size_t)row * K + k0 + k4);
            As[k4+0][row] = v.x; As[k4+1][row] = v.y; As[k4+2][row] = v.z; As[k4+3][row] = v.w;
            float4 u = *(const float4*)(Bb + (size_t)row * K + k0 + k4);
            Bs[k4+0][row] = u.x; Bs[k4+1][row] = u.y; Bs[k4+2][row] = u.z; Bs[k4+3][row] = u.w;
        }
        __syncthreads();
        #pragma unroll
        for (int k = 0; k < 16; k++) {
            float4 a0 = *(const float4*)&As[k][trow*8];
            float4 a1 = *(const float4*)&As[k][trow*8+4];
            float4 b0 = *(const float4*)&Bs[k][tcol*8];
            float4 b1 = *(const float4*)&Bs[k][tcol*8+4];
            float av[8] = {a0.x,a0.y,a0.z,a0.w,a1.x,a1.y,a1.z,a1.w};
            float bv[8] = {b0.x,b0.y,b0.z,b0.w,b1.x,b1.y,b1.z,b1.w};
            #pragma unroll
            for (int r = 0; r < 8; r++)
                #pragma unroll
                for (int c = 0; c < 8; c++) acc[r][c] += av[r] * bv[c];
        }
        __syncthreads();
    }
    float* Cb = C + (size_t)(blockIdx.y * 128) * N + blockIdx.x * 128;
    #pragma unroll
    for (int r = 0; r < 8; r++)
        #pragma unroll
        for (int c = 0; c < 8; c += 4) {
            float4 v = { acc[r][c], acc[r][c+1], acc[r][c+2], acc[r][c+3] };
            *(float4*)(Cb + (size_t)(trow*8 + r) * N + tcol*8 + c) = v;
        }
}

__global__ __launch_bounds__(256) void gemm_qkv_kernel(const float* __restrict__ x) {
    gemm_body(x, g_Wqkv, g_QKV, QKVN, DIM);
}
__global__ __launch_bounds__(256) void gemm_proj_kernel(float* __restrict__ out) {
    gemm_body(g_Y, g_Wp, out, DIM, DIM);
}

// ---------------------------------------------------------------------------
// 4) Q/K post-processing: RMSNorm (eps=2^-23) -> RoPE -> gain (q only).
//    One warp per (pos, slot); slots 0..15 = q heads, 16..19 = k heads.
// ---------------------------------------------------------------------------
__global__ __launch_bounds__(256) void qk_post_kernel(const float* __restrict__ gain) {
    int widx = blockIdx.x * 8 + (threadIdx.x >> 5);
    int lane = threadIdx.x & 31;
    if (widx >= SEQ * (NH + NKV)) return;
    int pos  = widx / (NH + NKV);
    int slot = widx - pos * (NH + NKV);

    float* p; float g = 1.f;
    if (slot < NH) { p = g_QKV + (size_t)pos * QKVN + slot * HD; g = gain[slot]; }
    else           { p = g_QKV + (size_t)pos * QKVN + DIM + (slot - NH) * HD; }

    float v0 = p[lane], v1 = p[lane+32], v2 = p[lane+64], v3 = p[lane+96];
    float ss = v0*v0 + v1*v1 + v2*v2 + v3*v3;
    #pragma unroll
    for (int o = 16; o > 0; o >>= 1) ss += __shfl_xor_sync(0xffffffffu, ss, o);
    float ms = ss * (1.f / 128.f) + 1.1920928955078125e-07f;
    float r  = rsqrtf(ms);
    r = r * (1.5f - 0.5f * ms * r * r);   // Newton refine
    v0 *= r; v1 *= r; v2 *= r; v3 *= r;

    const float* cr = g_cos + pos * 64;
    const float* sr = g_sin + pos * 64;
    float c0 = cr[lane], s0 = sr[lane], c1 = cr[lane+32], s1 = sr[lane+32];
    // reference rope: out1 = x1*cos + x2*sin ; out2 = -x1*sin + x2*cos
    float o0 =  v0 * c0 + v2 * s0;
    float o2 = -v0 * s0 + v2 * c0;
    float o1 =  v1 * c1 + v3 * s1;
    float o3 = -v1 * s1 + v3 * c1;
    p[lane]    = o0 * g;
    p[lane+32] = o1 * g;
    p[lane+64] = o2 * g;
    p[lane+96] = o3 * g;
}

// ---------------------------------------------------------------------------
// 5) Flash-style causal GQA attention, fp32.
//    Block = (q-tile of 64 rows, head). 256 threads. Streams 64-wide KV tiles
//    with online softmax. Dynamic smem ~117 KB.
// ---------------------------------------------------------------------------
#define QS_STRIDE 68   // 64 + 4 pad (keeps float4 alignment, breaks store conflicts)
#define SS_STRIDE 65

__global__ __launch_bounds__(256) void flash_kernel() {
    extern __shared__ float sm[];
    float* Qs    = sm;                     // [128][68]  (k-major, transposed)
    float* Ks    = Qs + 128 * QS_STRIDE;   // [128][68]
    float* Vs    = Ks + 128 * QS_STRIDE;   // [64][128]
    float* Ss    = Vs + 64 * 128;          // [64][65]
    float* alpha = Ss + 64 * SS_STRIDE;    // [64]
    float* linv  = alpha + 64;             // [64]

    int qtile = gridDim.x - 1 - blockIdx.x;   // longest blocks launch first
    int h     = blockIdx.y;
    int kvh   = h >> 2;                        // groups = 4
    int qbase = qtile * 64;
    int tid   = threadIdx.x;
    const float scale = 0.08838834764831845f;  // 1/sqrt(128)

    // --- Load Q tile transposed: Qs[k][m] ---
    const float* qptr = g_QKV + (size_t)qbase * QKVN + h * HD;
    #pragma unroll
    for (int it = 0; it < 8; it++) {
        int l  = it * 256 + tid;
        int m  = l >> 5;
        int k4 = (l & 31) * 4;
        float4 v = *(const float4*)(qptr + (size_t)m * QKVN + k4);
        Qs[(k4+0)*QS_STRIDE + m] = v.x;
        Qs[(k4+1)*QS_STRIDE + m] = v.y;
        Qs[(k4+2)*QS_STRIDE + m] = v.z;
        Qs[(k4+3)*QS_STRIDE + m] = v.w;
    }

    int trow = tid >> 4;   // 0..15 : owns 4 q-rows (S) / 4 q-rows (O)
    int tcol = tid & 15;   // 0..15 : owns 4 kv-cols (S) / 8 dims (O)

    float oacc[4][8];
    #pragma unroll
    for (int r = 0; r < 4; r++)
        #pragma unroll
        for (int c = 0; c < 8; c++) oacc[r][c] = 0.f;
    float m_r = -1e30f, l_r = 0.f;   // per-row state, valid for tid<64

    for (int j = 0; j <= qtile; j++) {
        int kvbase = j * 64;
        __syncthreads();   // protect previous iteration's Ss/Vs reads + Q load
        // --- Load K (transposed) and V tiles ---
        const float* kptr = g_QKV + (size_t)kvbase * QKVN + DIM + kvh * HD;
        const float* vptr = g_QKV + (size_t)kvbase * QKVN + DIM + KVDIM + kvh * HD;
        #pragma unroll
        for (int it = 0; it < 8; it++) {
            int l  = it * 256 + tid;
            int n  = l >> 5;
            int k4 = (l & 31) * 4;
            float4 v = *(const float4*)(kptr + (size_t)n * QKVN + k4);
            Ks[(k4+0)*QS_STRIDE + n] = v.x;
            Ks[(k4+1)*QS_STRIDE + n] = v.y;
            Ks[(k4+2)*QS_STRIDE + n] = v.z;
            Ks[(k4+3)*QS_STRIDE + n] = v.w;
            float4 u = *(const float4*)(vptr + (size_t)n * QKVN + k4);
            *(float4*)(Vs + n * 128 + k4) = u;
        }
        __syncthreads();

        // --- S = Q @ K^T (4x4 micro-tile per thread) ---
        float sacc[4][4];
        #pragma unroll
        for (int r = 0; r < 4; r++)
            #pragma unroll
            for (int c = 0; c < 4; c++) sacc[r][c] = 0.f;
        #pragma unroll 4
        for (int k = 0; k < 128; k++) {
            float4 a = *(const float4*)(Qs + k * QS_STRIDE + trow * 4);
            float4 b = *(const float4*)(Ks + k * QS_STRIDE + tcol * 4);
            float av[4] = {a.x, a.y, a.z, a.w};
            float bv[4] = {b.x, b.y, b.z, b.w};
            #pragma unroll
            for (int r = 0; r < 4; r++)
                #pragma unroll
                for (int c = 0; c < 4; c++) sacc[r][c] += av[r] * bv[c];
        }
        // scaled + causal-masked write
        #pragma unroll
        for (int r = 0; r < 4; r++) {
            int mg = qbase + trow * 4 + r;
            #pragma unroll
            for (int c = 0; c < 4; c++) {
                int ng = kvbase + tcol * 4 + c;
                Ss[(trow*4 + r) * SS_STRIDE + tcol*4 + c] =
                    (ng <= mg) ? sacc[r][c] * scale : -1e30f;
            }
        }
        __syncthreads();

        // --- Online softmax update (one thread per row) ---
        if (tid < 64) {
            float mx = m_r;
            #pragma unroll 8
            for (int n = 0; n < 64; n++) mx = fmaxf(mx, Ss[tid * SS_STRIDE + n]);
            float al = expf(m_r - mx);
            float ls = 0.f;
            #pragma unroll 8
            for (int n = 0; n < 64; n++) {
                float p = expf(Ss[tid * SS_STRIDE + n] - mx);
                Ss[tid * SS_STRIDE + n] = p;
                ls += p;
            }
            l_r = l_r * al + ls;
            m_r = mx;
            alpha[tid] = al;
        }
        __syncthreads();

        // --- O = O*alpha + P @ V ---
        float al0 = alpha[trow*4+0], al1 = alpha[trow*4+1];
        float al2 = alpha[trow*4+2], al3 = alpha[trow*4+3];
        #pragma unroll
        for (int c = 0; c < 8; c++) {
            oacc[0][c] *= al0; oacc[1][c] *= al1;
            oacc[2][c] *= al2; oacc[3][c] *= al3;
        }
        #pragma unroll 2
        for (int k = 0; k < 64; k++) {
            float a0 = Ss[(trow*4+0) * SS_STRIDE + k];
            float a1 = Ss[(trow*4+1) * SS_STRIDE + k];
            float a2 = Ss[(trow*4+2) * SS_STRIDE + k];
            float a3 = Ss[(trow*4+3) * SS_STRIDE + k];
            float4 b0 = *(const float4*)(Vs + k * 128 + tcol * 8);
            float4 b1 = *(const float4*)(Vs + k * 128 + tcol * 8 + 4);
            float bv[8] = {b0.x,b0.y,b0.z,b0.w,b1.x,b1.y,b1.z,b1.w};
            #pragma unroll
            for (int c = 0; c < 8; c++) {
                oacc[0][c] += a0 * bv[c];
                oacc[1][c] += a1 * bv[c];
                oacc[2][c] += a2 * bv[c];
                oacc[3][c] += a3 * bv[c];
            }
        }
    }

    // --- Normalize and write Y[pos][h*128+d] ---
    __syncthreads();
    if (tid < 64) linv[tid] = 1.f / l_r;
    __syncthreads();
    #pragma unroll
    for (int r = 0; r < 4; r++) {
        float li = linv[trow*4 + r];
        float4 v0 = { oacc[r][0]*li, oacc[r][1]*li, oacc[r][2]*li, oacc[r][3]*li };
        float4 v1 = { oacc[r][4]*li, oacc[r][5]*li, oacc[r][6]*li, oacc[r][7]*li };
        float* dst = g_Y + (size_t)(qbase + trow*4 + r) * DIM + h * HD + tcol * 8;
        *(float4*)dst       = v0;
        *(float4*)(dst + 4) = v1;
    }
}

// ---------------------------------------------------------------------------
// Launch
// ---------------------------------------------------------------------------
static const int FLASH_SMEM =
    (2 * 128 * QS_STRIDE + 64 * 128 + 64 * SS_STRIDE + 128) * (int)sizeof(float);

extern "C" void kernel_launch(void* const* d_in, const int* in_sizes, int n_in,
                              void* d_out, int out_size)
{
    const float* x    = (const float*)d_in[0];
    const float* wq   = (const float*)d_in[1];
    const float* wk   = (const float*)d_in[2];
    const float* wv   = (const float*)d_in[3];
    const float* wp   = (const float*)d_in[4];
    const float* gain = (const float*)d_in[5];
    float* out = (float*)d_out;

    cudaFuncSetAttribute(flash_kernel,
                         cudaFuncAttributeMaxDynamicSharedMemorySize, FLASH_SMEM);

    // 1) RoPE tables (double precision)
    rope_table_kernel<<<(SEQ * (HD/2) + 255) / 256, 256>>>();
    // 2) BitLinear quantization of all weights
    quantize_kernel<<<NROWS_W, 256>>>(wq, wk, wv, wp);
    // 3) QKV = x @ Wqkv^T   [4096 x 3072]
    gemm_qkv_kernel<<<dim3(QKVN / 128, SEQ / 128), 256>>>(x);
    // 4) RMSNorm + RoPE + gain on Q and K heads
    qk_post_kernel<<<(SEQ * (NH + NKV) + 7) / 8, 256>>>(gain);
    // 5) Causal GQA flash attention -> Y
    flash_kernel<<<dim3(SEQ / 64, NH), 256, FLASH_SMEM>>>();
    // 6) out = Y @ Wp^T
    gemm_proj_kernel<<<dim3(DIM / 128, SEQ / 128), 256>>>(out);
}

// round 9
// speedup vs baseline: 3.8804x; 3.8804x over previous
#include <cuda_runtime.h>
#include <cuda_bf16.h>
#include <math.h>

// ---------------------------------------------------------------------------
// Problem constants
// ---------------------------------------------------------------------------
#define SEQ      4096
#define DIM      2048
#define NH       16
#define NKV      4
#define HD       128
#define KVDIM    (NKV*HD)          // 512
#define QKVN     (DIM + 2*KVDIM)   // 3072
#define NROWS_W  (QKVN + DIM)      // 5120 quantize rows

// ---------------------------------------------------------------------------
// Device-global scratch (no cudaMalloc allowed)
// ---------------------------------------------------------------------------
__device__ float g_Wqkv[QKVN * DIM];   // TERNARY {-1,0,1} [q|k|v] weights [3072][2048]
__device__ float g_Wp  [DIM  * DIM];   // TERNARY proj weights [2048][2048]
__device__ float g_sqkv[QKVN];         // per-row scales for qkv weights
__device__ float g_sp  [DIM];          // per-row scales for proj weights
__device__ float g_QKV [SEQ  * QKVN];  // x @ W^T (scaled) : [4096][3072]
__device__ float g_Y   [SEQ  * DIM];   // attention output [4096][2048]
__device__ float g_cos [SEQ * (HD/2)];
__device__ float g_sin [SEQ * (HD/2)];

// ---------------------------------------------------------------------------
// mma.sync m16n8k8 tf32 helpers
// ---------------------------------------------------------------------------
__device__ __forceinline__ float to_tf32(float x) {
    unsigned r;
    asm("cvt.rna.tf32.f32 %0, %1;" : "=r"(r) : "f"(x));
    return __uint_as_float(r);
}

__device__ __forceinline__ void mma_tf32(float d[4], const unsigned a[4], const unsigned b[2]) {
    asm volatile(
        "mma.sync.aligned.m16n8k8.row.col.f32.tf32.tf32.f32 "
        "{%0,%1,%2,%3},{%4,%5,%6,%7},{%8,%9},{%0,%1,%2,%3};"
        : "+f"(d[0]), "+f"(d[1]), "+f"(d[2]), "+f"(d[3])
        : "r"(a[0]), "r"(a[1]), "r"(a[2]), "r"(a[3]), "r"(b[0]), "r"(b[1]));
}

// ---------------------------------------------------------------------------
// 1) RoPE tables in double precision
// ---------------------------------------------------------------------------
__global__ void rope_table_kernel() {
    int idx = blockIdx.x * blockDim.x + threadIdx.x;
    if (idx >= SEQ * (HD/2)) return;
    int t = idx >> 6;
    int j = idx & 63;
    double invf = pow(10000.0, -(double)j / 64.0);
    double sn, cn;
    sincos((double)t * invf, &sn, &cn);
    g_cos[idx] = (float)cn;
    g_sin[idx] = (float)sn;
}

// ---------------------------------------------------------------------------
// 2) BitLinear quantize -> TERNARY weights + per-row scale.
// ---------------------------------------------------------------------------
__global__ __launch_bounds__(256) void quantize_kernel(
    const float* __restrict__ wq, const float* __restrict__ wk,
    const float* __restrict__ wv, const float* __restrict__ wp)
{
    int row = blockIdx.x;
    const float* src; float* dst; float* sdst;
    if      (row < DIM)        { src = wq + (size_t)row * DIM;                 dst = g_Wqkv + (size_t)row * DIM; sdst = g_sqkv + row; }
    else if (row < DIM + KVDIM){ src = wk + (size_t)(row - DIM) * DIM;         dst = g_Wqkv + (size_t)row * DIM; sdst = g_sqkv + row; }
    else if (row < QKVN)       { src = wv + (size_t)(row - DIM - KVDIM) * DIM; dst = g_Wqkv + (size_t)row * DIM; sdst = g_sqkv + row; }
    else                       { src = wp + (size_t)(row - QKVN) * DIM;        dst = g_Wp + (size_t)(row - QKVN) * DIM; sdst = g_sp + (row - QKVN); }

    __shared__ double red[256];
    double acc = 0.0;
    for (int k = threadIdx.x; k < DIM; k += 256) acc += (double)fabsf(src[k]);
    red[threadIdx.x] = acc;
    __syncthreads();
    for (int off = 128; off > 0; off >>= 1) {
        if (threadIdx.x < off) red[threadIdx.x] += red[threadIdx.x + off];
        __syncthreads();
    }
    float s = fmaxf((float)(red[0] / (double)DIM), 1e-5f);
    if (threadIdx.x == 0) *sdst = s;
    for (int k = threadIdx.x; k < DIM; k += 256) {
        float w = rintf(src[k] / s);
        dst[k] = fminf(fmaxf(w, -1.f), 1.f);   // exact in tf32
    }
}

// ---------------------------------------------------------------------------
// 3) TF32 tensor-core GEMM: C[M,N] = (A[M,K] @ T[N,K]^T) * s[n]
//    BM=BN=128, BK=32, 256 threads = 8 warps (4x2), warp tile 32x64.
// ---------------------------------------------------------------------------
__device__ __forceinline__ void gemm_core(
    const float* __restrict__ A, const float* __restrict__ B,
    const float* __restrict__ sc, float* __restrict__ C, int N)
{
    __shared__ float As[128 * 36];
    __shared__ float Bs[128 * 36];
    const int K = DIM;
    int tid = threadIdx.x, warp = tid >> 5, lane = tid & 31;
    int g = lane >> 2, t = lane & 3;
    int wm = (warp & 3) * 32, wn = (warp >> 2) * 64;
    const float* Ab = A + (size_t)blockIdx.y * 128 * K;
    const float* Bb = B + (size_t)blockIdx.x * 128 * K;

    float acc[2][8][4];
    #pragma unroll
    for (int mt = 0; mt < 2; mt++)
        #pragma unroll
        for (int nt = 0; nt < 8; nt++)
            #pragma unroll
            for (int r = 0; r < 4; r++) acc[mt][nt][r] = 0.f;

    for (int k0 = 0; k0 < K; k0 += 32) {
        __syncthreads();
        #pragma unroll
        for (int i = 0; i < 4; i++) {
            int l = tid + i * 256;            // 0..1023 : 128 rows x 8 float4
            int row = l >> 3, kq = (l & 7) * 4;
            float4 v = *(const float4*)(Ab + (size_t)row * K + k0 + kq);
            v.x = to_tf32(v.x); v.y = to_tf32(v.y); v.z = to_tf32(v.z); v.w = to_tf32(v.w);
            *(float4*)(As + row * 36 + kq) = v;
            float4 u = *(const float4*)(Bb + (size_t)row * K + k0 + kq);  // ternary: tf32-exact
            *(float4*)(Bs + row * 36 + kq) = u;
        }
        __syncthreads();
        #pragma unroll
        for (int kk = 0; kk < 32; kk += 8) {
            unsigned a[2][4];
            #pragma unroll
            for (int mt = 0; mt < 2; mt++) {
                const float* ap = As + (wm + mt * 16 + g) * 36 + kk + t;
                a[mt][0] = __float_as_uint(ap[0]);
                a[mt][1] = __float_as_uint(ap[8 * 36]);
                a[mt][2] = __float_as_uint(ap[4]);
                a[mt][3] = __float_as_uint(ap[8 * 36 + 4]);
            }
            #pragma unroll
            for (int nt = 0; nt < 8; nt++) {
                unsigned b[2];
                const float* bp = Bs + (wn + nt * 8 + g) * 36 + kk + t;
                b[0] = __float_as_uint(bp[0]);
                b[1] = __float_as_uint(bp[4]);
                mma_tf32(acc[0][nt], a[0], b);
                mma_tf32(acc[1][nt], a[1], b);
            }
        }
    }
    int brow = blockIdx.y * 128, bcol = blockIdx.x * 128;
    #pragma unroll
    for (int mt = 0; mt < 2; mt++) {
        int r0 = brow + wm + mt * 16 + g;
        #pragma unroll
        for (int nt = 0; nt < 8; nt++) {
            int c = bcol + wn + nt * 8 + 2 * t;
            float s0 = sc[c], s1 = sc[c + 1];
            *(float2*)(C + (size_t)r0 * N + c)       = make_float2(acc[mt][nt][0] * s0, acc[mt][nt][1] * s1);
            *(float2*)(C + (size_t)(r0 + 8) * N + c) = make_float2(acc[mt][nt][2] * s0, acc[mt][nt][3] * s1);
        }
    }
}

__global__ __launch_bounds__(256, 2) void gemm_qkv_kernel(const float* __restrict__ x) {
    gemm_core(x, g_Wqkv, g_sqkv, g_QKV, QKVN);
}
__global__ __launch_bounds__(256, 2) void gemm_proj_kernel(float* __restrict__ out) {
    gemm_core(g_Y, g_Wp, g_sp, out, DIM);
}

// ---------------------------------------------------------------------------
// 4) Q/K post: RMSNorm (eps=2^-23) -> RoPE -> gain (q only). One warp/(pos,slot).
// ---------------------------------------------------------------------------
__global__ __launch_bounds__(256) void qk_post_kernel(const float* __restrict__ gain) {
    int widx = blockIdx.x * 8 + (threadIdx.x >> 5);
    int lane = threadIdx.x & 31;
    if (widx >= SEQ * (NH + NKV)) return;
    int pos  = widx / (NH + NKV);
    int slot = widx - pos * (NH + NKV);

    float* p; float gv = 1.f;
    if (slot < NH) { p = g_QKV + (size_t)pos * QKVN + slot * HD; gv = gain[slot]; }
    else           { p = g_QKV + (size_t)pos * QKVN + DIM + (slot - NH) * HD; }

    float v0 = p[lane], v1 = p[lane+32], v2 = p[lane+64], v3 = p[lane+96];
    float ss = v0*v0 + v1*v1 + v2*v2 + v3*v3;
    #pragma unroll
    for (int o = 16; o > 0; o >>= 1) ss += __shfl_xor_sync(0xffffffffu, ss, o);
    float ms = ss * (1.f / 128.f) + 1.1920928955078125e-07f;
    float r  = rsqrtf(ms);
    r = r * (1.5f - 0.5f * ms * r * r);
    v0 *= r; v1 *= r; v2 *= r; v3 *= r;

    const float* cr = g_cos + pos * 64;
    const float* sr = g_sin + pos * 64;
    float c0 = cr[lane], s0 = sr[lane], c1 = cr[lane+32], s1 = sr[lane+32];
    float o0 =  v0 * c0 + v2 * s0;
    float o2 = -v0 * s0 + v2 * c0;
    float o1 =  v1 * c1 + v3 * s1;
    float o3 = -v1 * s1 + v3 * c1;
    p[lane]    = o0 * gv;
    p[lane+32] = o1 * gv;
    p[lane+64] = o2 * gv;
    p[lane+96] = o3 * gv;
}

// ---------------------------------------------------------------------------
// 5) TF32 tensor-core causal GQA flash attention.
//    Block = (128 q-rows, head), 8 warps x 16 rows, KV tiles of 64.
//    Smem: Qs[128][132], Ks[64][132], Vs[64][136], Ps[128][68]  = 171 KB
// ---------------------------------------------------------------------------
#define QSTR 132
#define VSTR 136
#define PSTR 68

__global__ __launch_bounds__(256, 1) void flash_kernel() {
    extern __shared__ float sm[];
    float* Qs = sm;                   // [128][132]
    float* Ks = Qs + 128 * QSTR;      // [64][132]
    float* Vs = Ks + 64 * QSTR;       // [64][136]
    float* Ps = Vs + 64 * VSTR;       // [128][68]

    int qtile = gridDim.x - 1 - blockIdx.x;   // longest first
    int h = blockIdx.y, kvh = h >> 2;
    int qbase = qtile * 128;
    int tid = threadIdx.x, warp = tid >> 5, lane = tid & 31;
    int g = lane >> 2, t = lane & 3;
    int wbase = warp * 16;
    const float scale = 0.08838834764831845f;
    const float L2E = 1.4426950408889634f;

    // Load Q tile (tf32): 128 rows x 32 float4
    const float* qp = g_QKV + (size_t)qbase * QKVN + h * HD;
    #pragma unroll
    for (int i = 0; i < 16; i++) {
        int l = tid + i * 256;            // 0..4095
        int row = l >> 5, kq = (l & 31) * 4;
        float4 v = *(const float4*)(qp + (size_t)row * QKVN + kq);
        v.x = to_tf32(v.x); v.y = to_tf32(v.y); v.z = to_tf32(v.z); v.w = to_tf32(v.w);
        *(float4*)(Qs + row * QSTR + kq) = v;
    }

    float oacc[16][4];
    #pragma unroll
    for (int nt = 0; nt < 16; nt++)
        #pragma unroll
        for (int r = 0; r < 4; r++) oacc[nt][r] = 0.f;
    float m0 = -1e30f, m1 = -1e30f, l0 = 0.f, l1 = 0.f;

    int row0 = qbase + wbase + g, row1 = row0 + 8;
    int jmax = 2 * qtile + 1;

    for (int j = 0; j <= jmax; j++) {
        int kvbase = j * 64;
        __syncthreads();
        const float* kp = g_QKV + (size_t)kvbase * QKVN + DIM + kvh * HD;
        const float* vp = kp + KVDIM;
        #pragma unroll
        for (int i = 0; i < 8; i++) {
            int l = tid + i * 256;        // 0..2047 : 64 rows x 32 float4
            int row = l >> 5, kq = (l & 31) * 4;
            float4 v = *(const float4*)(kp + (size_t)row * QKVN + kq);
            v.x = to_tf32(v.x); v.y = to_tf32(v.y); v.z = to_tf32(v.z); v.w = to_tf32(v.w);
            *(float4*)(Ks + row * QSTR + kq) = v;
            float4 u = *(const float4*)(vp + (size_t)row * QKVN + kq);
            u.x = to_tf32(u.x); u.y = to_tf32(u.y); u.z = to_tf32(u.z); u.w = to_tf32(u.w);
            *(float4*)(Vs + row * VSTR + kq) = u;
        }
        __syncthreads();

        // --- S = Q @ K^T ---
        float sacc[8][4];
        #pragma unroll
        for (int nt = 0; nt < 8; nt++)
            #pragma unroll
            for (int r = 0; r < 4; r++) sacc[nt][r] = 0.f;
        #pragma unroll
        for (int k8 = 0; k8 < 128; k8 += 8) {
            unsigned a[4];
            const float* ap = Qs + (wbase + g) * QSTR + k8 + t;
            a[0] = __float_as_uint(ap[0]);
            a[1] = __float_as_uint(ap[8 * QSTR]);
            a[2] = __float_as_uint(ap[4]);
            a[3] = __float_as_uint(ap[8 * QSTR + 4]);
            #pragma unroll
            for (int nt = 0; nt < 8; nt++) {
                unsigned b[2];
                const float* bp = Ks + (nt * 8 + g) * QSTR + k8 + t;
                b[0] = __float_as_uint(bp[0]);
                b[1] = __float_as_uint(bp[4]);
                mma_tf32(sacc[nt], a, b);
            }
        }

        // --- scale + causal mask + online softmax (register, quad-shfl) ---
        float mn0 = m0, mn1 = m1;
        #pragma unroll
        for (int nt = 0; nt < 8; nt++) {
            int c0 = kvbase + nt * 8 + 2 * t, c1 = c0 + 1;
            float v0 = (c0 <= row0) ? sacc[nt][0] * scale : -1e30f;
            float v1 = (c1 <= row0) ? sacc[nt][1] * scale : -1e30f;
            float v2 = (c0 <= row1) ? sacc[nt][2] * scale : -1e30f;
            float v3 = (c1 <= row1) ? sacc[nt][3] * scale : -1e30f;
            sacc[nt][0] = v0; sacc[nt][1] = v1; sacc[nt][2] = v2; sacc[nt][3] = v3;
            mn0 = fmaxf(mn0, fmaxf(v0, v1));
            mn1 = fmaxf(mn1, fmaxf(v2, v3));
        }
        mn0 = fmaxf(mn0, __shfl_xor_sync(0xffffffffu, mn0, 1));
        mn0 = fmaxf(mn0, __shfl_xor_sync(0xffffffffu, mn0, 2));
        mn1 = fmaxf(mn1, __shfl_xor_sync(0xffffffffu, mn1, 1));
        mn1 = fmaxf(mn1, __shfl_xor_sync(0xffffffffu, mn1, 2));
        float a0 = exp2f((m0 - mn0) * L2E);
        float a1 = exp2f((m1 - mn1) * L2E);
        m0 = mn0; m1 = mn1;
        float s0 = 0.f, s1 = 0.f;
        float* pr0 = Ps + (wbase + g) * PSTR + 2 * t;
        float* pr1 = pr0 + 8 * PSTR;
        #pragma unroll
        for (int nt = 0; nt < 8; nt++) {
            float p0 = exp2f((sacc[nt][0] - m0) * L2E);
            float p1 = exp2f((sacc[nt][1] - m0) * L2E);
            float p2 = exp2f((sacc[nt][2] - m1) * L2E);
            float p3 = exp2f((sacc[nt][3] - m1) * L2E);
            s0 += p0 + p1; s1 += p2 + p3;
            *(float2*)(pr0 + nt * 8) = make_float2(to_tf32(p0), to_tf32(p1));
            *(float2*)(pr1 + nt * 8) = make_float2(to_tf32(p2), to_tf32(p3));
        }
        s0 += __shfl_xor_sync(0xffffffffu, s0, 1);
        s0 += __shfl_xor_sync(0xffffffffu, s0, 2);
        s1 += __shfl_xor_sync(0xffffffffu, s1, 1);
        s1 += __shfl_xor_sync(0xffffffffu, s1, 2);
        l0 = l0 * a0 + s0;
        l1 = l1 * a1 + s1;
        #pragma unroll
        for (int nt = 0; nt < 16; nt++) {
            oacc[nt][0] *= a0; oacc[nt][1] *= a0;
            oacc[nt][2] *= a1; oacc[nt][3] *= a1;
        }
        __syncwarp();

        // --- O += P @ V ---
        #pragma unroll
        for (int k8 = 0; k8 < 64; k8 += 8) {
            unsigned a[4];
            const float* ap = Ps + (wbase + g) * PSTR + k8 + t;
            a[0] = __float_as_uint(ap[0]);
            a[1] = __float_as_uint(ap[8 * PSTR]);
            a[2] = __float_as_uint(ap[4]);
            a[3] = __float_as_uint(ap[8 * PSTR + 4]);
            #pragma unroll
            for (int nt = 0; nt < 16; nt++) {
                unsigned b[2];
                const float* bp = Vs + (k8 + t) * VSTR + nt * 8 + g;
                b[0] = __float_as_uint(bp[0]);
                b[1] = __float_as_uint(bp[4 * VSTR]);
                mma_tf32(oacc[nt], a, b);
            }
        }
    }

    // --- epilogue: O /= l, write Y ---
    float i0 = 1.f / l0, i1 = 1.f / l1;
    float* y0 = g_Y + (size_t)(qbase + wbase + g) * DIM + h * HD + 2 * t;
    float* y1 = y0 + 8 * DIM;
    #pragma unroll
    for (int nt = 0; nt < 16; nt++) {
        *(float2*)(y0 + nt * 8) = make_float2(oacc[nt][0] * i0, oacc[nt][1] * i0);
        *(float2*)(y1 + nt * 8) = make_float2(oacc[nt][2] * i1, oacc[nt][3] * i1);
    }
}

// ---------------------------------------------------------------------------
// Launch
// ---------------------------------------------------------------------------
static const int FLASH_SMEM =
    (128 * QSTR + 64 * QSTR + 64 * VSTR + 128 * PSTR) * (int)sizeof(float);  // 171008

extern "C" void kernel_launch(void* const* d_in, const int* in_sizes, int n_in,
                              void* d_out, int out_size)
{
    const float* x    = (const float*)d_in[0];
    const float* wq   = (const float*)d_in[1];
    const float* wk   = (const float*)d_in[2];
    const float* wv   = (const float*)d_in[3];
    const float* wp   = (const float*)d_in[4];
    const float* gain = (const float*)d_in[5];
    float* out = (float*)d_out;

    cudaFuncSetAttribute(flash_kernel,
                         cudaFuncAttributeMaxDynamicSharedMemorySize, FLASH_SMEM);

    rope_table_kernel<<<(SEQ * (HD/2) + 255) / 256, 256>>>();
    quantize_kernel<<<NROWS_W, 256>>>(wq, wk, wv, wp);
    gemm_qkv_kernel<<<dim3(QKVN / 128, SEQ / 128), 256>>>(x);
    qk_post_kernel<<<(SEQ * (NH + NKV) + 7) / 8, 256>>>(gain);
    flash_kernel<<<dim3(SEQ / 128, NH), 256, FLASH_SMEM>>>();
    gemm_proj_kernel<<<dim3(DIM / 128, SEQ / 128), 256>>>(out);
}

// round 10
// speedup vs baseline: 3.9839x; 1.0267x over previous
#include <cuda_runtime.h>
#include <cuda_bf16.h>
#include <math.h>

// ---------------------------------------------------------------------------
// Problem constants
// ---------------------------------------------------------------------------
#define SEQ      4096
#define DIM      2048
#define NH       16
#define NKV      4
#define HD       128
#define KVDIM    (NKV*HD)          // 512
#define QKVN     (DIM + 2*KVDIM)   // 3072
#define NROWS_W  (QKVN + DIM)      // 5120 quantize rows

// ---------------------------------------------------------------------------
// Device-global scratch (no cudaMalloc allowed)
// ---------------------------------------------------------------------------
__device__ float  g_Wqkv[QKVN * DIM];   // TERNARY {-1,0,1} [q|k|v] weights [3072][2048]
__device__ float  g_Wp  [DIM  * DIM];   // TERNARY proj weights [2048][2048]
__device__ float  g_sqkv[QKVN];         // per-row scales for qkv weights
__device__ float  g_sp  [DIM];          // per-row scales for proj weights
__device__ float  g_QKV [SEQ  * QKVN];  // x @ W^T (scaled) : [4096][3072]
__device__ float  g_Y   [SEQ  * DIM];   // attention output [4096][2048]
__device__ float  g_cos [SEQ * (HD/2)];
__device__ float  g_sin [SEQ * (HD/2)];
__device__ double g_invf[HD/2];         // RoPE inverse frequencies (fp64)

// ---------------------------------------------------------------------------
// helpers
// ---------------------------------------------------------------------------
__device__ __forceinline__ float to_tf32(float x) {
    unsigned r;
    asm("cvt.rna.tf32.f32 %0, %1;" : "=r"(r) : "f"(x));
    return __uint_as_float(r);
}
__device__ __forceinline__ unsigned to_tf32u(float x) {
    unsigned r;
    asm("cvt.rna.tf32.f32 %0, %1;" : "=r"(r) : "f"(x));
    return r;
}

__device__ __forceinline__ void mma_tf32(float d[4], const unsigned a[4], const unsigned b[2]) {
    asm volatile(
        "mma.sync.aligned.m16n8k8.row.col.f32.tf32.tf32.f32 "
        "{%0,%1,%2,%3},{%4,%5,%6,%7},{%8,%9},{%0,%1,%2,%3};"
        : "+f"(d[0]), "+f"(d[1]), "+f"(d[2]), "+f"(d[3])
        : "r"(a[0]), "r"(a[1]), "r"(a[2]), "r"(a[3]), "r"(b[0]), "r"(b[1]));
}

__device__ __forceinline__ void cp_async16(float* smem_dst, const float* gmem_src) {
    unsigned s = (unsigned)__cvta_generic_to_shared(smem_dst);
    asm volatile("cp.async.cg.shared.global [%0], [%1], 16;" :: "r"(s), "l"(gmem_src));
}
#define CP_COMMIT()  asm volatile("cp.async.commit_group;")
#define CP_WAIT(N)   asm volatile("cp.async.wait_group %0;" :: "n"(N))

// ---------------------------------------------------------------------------
// 1) RoPE tables: invf in fp64 (64 pows total), then fp64 range reduction +
//    fast fp32 sincos on |r|<=pi (accurate to ~1e-6, fast-math-proof).
// ---------------------------------------------------------------------------
__global__ void invf_kernel() {
    int j = threadIdx.x;
    if (j < HD/2) g_invf[j] = pow(10000.0, -(double)j / 64.0);
}

__global__ void rope_table_kernel() {
    int idx = blockIdx.x * blockDim.x + threadIdx.x;
    if (idx >= SEQ * (HD/2)) return;
    int t = idx >> 6;
    int j = idx & 63;
    double ang = (double)t * g_invf[j];
    double q   = rint(ang * 0.15915494309189535);          // 1/(2*pi)
    float  r   = (float)(ang - q * 6.283185307179586476);  // |r| <= pi
    float sn, cn;
    __sincosf(r, &sn, &cn);
    g_cos[idx] = cn;
    g_sin[idx] = sn;
}

// ---------------------------------------------------------------------------
// 2) BitLinear quantize -> TERNARY weights + per-row scale.
// ---------------------------------------------------------------------------
__global__ __launch_bounds__(256) void quantize_kernel(
    const float* __restrict__ wq, const float* __restrict__ wk,
    const float* __restrict__ wv, const float* __restrict__ wp)
{
    int row = blockIdx.x;
    const float* src; float* dst; float* sdst;
    if      (row < DIM)        { src = wq + (size_t)row * DIM;                 dst = g_Wqkv + (size_t)row * DIM; sdst = g_sqkv + row; }
    else if (row < DIM + KVDIM){ src = wk + (size_t)(row - DIM) * DIM;         dst = g_Wqkv + (size_t)row * DIM; sdst = g_sqkv + row; }
    else if (row < QKVN)       { src = wv + (size_t)(row - DIM - KVDIM) * DIM; dst = g_Wqkv + (size_t)row * DIM; sdst = g_sqkv + row; }
    else                       { src = wp + (size_t)(row - QKVN) * DIM;        dst = g_Wp + (size_t)(row - QKVN) * DIM; sdst = g_sp + (row - QKVN); }

    __shared__ double red[256];
    double acc = 0.0;
    for (int k = threadIdx.x; k < DIM; k += 256) acc += (double)fabsf(src[k]);
    red[threadIdx.x] = acc;
    __syncthreads();
    for (int off = 128; off > 0; off >>= 1) {
        if (threadIdx.x < off) red[threadIdx.x] += red[threadIdx.x + off];
        __syncthreads();
    }
    float s = fmaxf((float)(red[0] / (double)DIM), 1e-5f);
    if (threadIdx.x == 0) *sdst = s;
    for (int k = threadIdx.x; k < DIM; k += 256) {
        float w = rintf(src[k] / s);
        dst[k] = fminf(fmaxf(w, -1.f), 1.f);   // exact in tf32
    }
}

// ---------------------------------------------------------------------------
// 3) TF32 GEMM, cp.async double-buffered: C[M,N] = (A @ T^T) * s[n]
//    BM=BN=128, BK=32, 256 threads = 8 warps (4x2), warp tile 32x64.
//    A stored raw f32 (cvt at fragment read); B ternary = tf32-exact.
// ---------------------------------------------------------------------------
#define GSTG 4608   // 128*36 floats per stage per operand

__device__ __forceinline__ void gemm_core(
    const float* __restrict__ A, const float* __restrict__ B,
    const float* __restrict__ sc, float* __restrict__ C, int N)
{
    extern __shared__ float smg[];
    float* As = smg;              // [2][128*36]
    float* Bs = smg + 2 * GSTG;   // [2][128*36]
    const int K = DIM;
    int tid = threadIdx.x, warp = tid >> 5, lane = tid & 31;
    int g = lane >> 2, t = lane & 3;
    int wm = (warp & 3) * 32, wn = (warp >> 2) * 64;
    const float* Ab = A + (size_t)blockIdx.y * 128 * K;
    const float* Bb = B + (size_t)blockIdx.x * 128 * K;

    float acc[2][8][4];
    #pragma unroll
    for (int mt = 0; mt < 2; mt++)
        #pragma unroll
        for (int nt = 0; nt < 8; nt++)
            #pragma unroll
            for (int r = 0; r < 4; r++) acc[mt][nt][r] = 0.f;

    // stage loader: 128 rows x 8 float4 per operand
    auto load_stage = [&](int stage, int k0) {
        float* Ad = As + stage * GSTG;
        float* Bd = Bs + stage * GSTG;
        #pragma unroll
        for (int i = 0; i < 4; i++) {
            int l = tid + i * 256;
            int row = l >> 3, kq = (l & 7) * 4;
            cp_async16(Ad + row * 36 + kq, Ab + (size_t)row * K + k0 + kq);
            cp_async16(Bd + row * 36 + kq, Bb + (size_t)row * K + k0 + kq);
        }
        CP_COMMIT();
    };

    load_stage(0, 0);
    const int nIter = K / 32;   // 64
    for (int it = 0; it < nIter; it++) {
        CP_WAIT(0);
        __syncthreads();
        if (it + 1 < nIter) load_stage((it + 1) & 1, (it + 1) * 32);

        const float* Ac = As + (it & 1) * GSTG;
        const float* Bc = Bs + (it & 1) * GSTG;
        #pragma unroll
        for (int kk = 0; kk < 32; kk += 8) {
            unsigned a[2][4];
            #pragma unroll
            for (int mt = 0; mt < 2; mt++) {
                const float* ap = Ac + (wm + mt * 16 + g) * 36 + kk + t;
                a[mt][0] = to_tf32u(ap[0]);
                a[mt][1] = to_tf32u(ap[8 * 36]);
                a[mt][2] = to_tf32u(ap[4]);
                a[mt][3] = to_tf32u(ap[8 * 36 + 4]);
            }
            #pragma unroll
            for (int nt = 0; nt < 8; nt++) {
                unsigned b[2];
                const float* bp = Bc + (wn + nt * 8 + g) * 36 + kk + t;
                b[0] = __float_as_uint(bp[0]);   // ternary: exact tf32
                b[1] = __float_as_uint(bp[4]);
                mma_tf32(acc[0][nt], a[0], b);
                mma_tf32(acc[1][nt], a[1], b);
            }
        }
        __syncthreads();
    }

    int brow = blockIdx.y * 128, bcol = blockIdx.x * 128;
    #pragma unroll
    for (int mt = 0; mt < 2; mt++) {
        int r0 = brow + wm + mt * 16 + g;
        #pragma unroll
        for (int nt = 0; nt < 8; nt++) {
            int c = bcol + wn + nt * 8 + 2 * t;
            float s0 = sc[c], s1 = sc[c + 1];
            *(float2*)(C + (size_t)r0 * N + c)       = make_float2(acc[mt][nt][0] * s0, acc[mt][nt][1] * s1);
            *(float2*)(C + (size_t)(r0 + 8) * N + c) = make_float2(acc[mt][nt][2] * s0, acc[mt][nt][3] * s1);
        }
    }
}

__global__ __launch_bounds__(256, 2) void gemm_qkv_kernel(const float* __restrict__ x) {
    gemm_core(x, g_Wqkv, g_sqkv, g_QKV, QKVN);
}
__global__ __launch_bounds__(256, 2) void gemm_proj_kernel(float* __restrict__ out) {
    gemm_core(g_Y, g_Wp, g_sp, out, DIM);
}
static const int GEMM_SMEM = 4 * GSTG * (int)sizeof(float);  // 73728

// ---------------------------------------------------------------------------
// 4) Q/K post: RMSNorm (eps=2^-23) -> RoPE -> gain (q only). One warp/(pos,slot).
// ---------------------------------------------------------------------------
__global__ __launch_bounds__(256) void qk_post_kernel(const float* __restrict__ gain) {
    int widx = blockIdx.x * 8 + (threadIdx.x >> 5);
    int lane = threadIdx.x & 31;
    if (widx >= SEQ * (NH + NKV)) return;
    int pos  = widx / (NH + NKV);
    int slot = widx - pos * (NH + NKV);

    float* p; float gv = 1.f;
    if (slot < NH) { p = g_QKV + (size_t)pos * QKVN + slot * HD; gv = gain[slot]; }
    else           { p = g_QKV + (size_t)pos * QKVN + DIM + (slot - NH) * HD; }

    float v0 = p[lane], v1 = p[lane+32], v2 = p[lane+64], v3 = p[lane+96];
    float ss = v0*v0 + v1*v1 + v2*v2 + v3*v3;
    #pragma unroll
    for (int o = 16; o > 0; o >>= 1) ss += __shfl_xor_sync(0xffffffffu, ss, o);
    float ms = ss * (1.f / 128.f) + 1.1920928955078125e-07f;
    float r  = rsqrtf(ms);
    r = r * (1.5f - 0.5f * ms * r * r);
    v0 *= r; v1 *= r; v2 *= r; v3 *= r;

    const float* cr = g_cos + pos * 64;
    const float* sr = g_sin + pos * 64;
    float c0 = cr[lane], s0 = sr[lane], c1 = cr[lane+32], s1 = sr[lane+32];
    float o0 =  v0 * c0 + v2 * s0;
    float o2 = -v0 * s0 + v2 * c0;
    float o1 =  v1 * c1 + v3 * s1;
    float o3 = -v1 * s1 + v3 * c1;
    p[lane]    = o0 * gv;
    p[lane+32] = o1 * gv;
    p[lane+64] = o2 * gv;
    p[lane+96] = o3 * gv;
}

// ---------------------------------------------------------------------------
// 5) TF32 flash attention with cp.async pipelining.
//    Block = (128 q-rows, head). K double-buffered (prefetch j+1 one full
//    iteration early); V loaded async overlapping S-MMA + softmax.
//    Smem: Qs[128][132] + Ks[2][64][132] + Vs[64][136] + Ps[128][68] = 204.8KB
// ---------------------------------------------------------------------------
#define QSTR 132
#define VSTR 136
#define PSTR 68

__global__ __launch_bounds__(256, 1) void flash_kernel() {
    extern __shared__ float sm[];
    float* Qs  = sm;                    // [128][132]  (tf32-rounded)
    float* Ks0 = Qs  + 128 * QSTR;      // [64][132]   raw f32
    float* Ks1 = Ks0 + 64 * QSTR;       // [64][132]   raw f32
    float* Vs  = Ks1 + 64 * QSTR;       // [64][136]   raw f32
    float* Ps  = Vs  + 64 * VSTR;       // [128][68]   tf32-rounded

    int qtile = gridDim.x - 1 - blockIdx.x;   // longest first
    int h = blockIdx.y, kvh = h >> 2;
    int qbase = qtile * 128;
    int tid = threadIdx.x, warp = tid >> 5, lane = tid & 31;
    int g = lane >> 2, t = lane & 3;
    int wbase = warp * 16;
    const float scale = 0.08838834764831845f;
    const float L2E = 1.4426950408889634f;

    // Load Q tile (tf32 at store): 128 rows x 32 float4
    const float* qp = g_QKV + (size_t)qbase * QKVN + h * HD;
    #pragma unroll
    for (int i = 0; i < 16; i++) {
        int l = tid + i * 256;
        int row = l >> 5, kq = (l & 31) * 4;
        float4 v = *(const float4*)(qp + (size_t)row * QKVN + kq);
        v.x = to_tf32(v.x); v.y = to_tf32(v.y); v.z = to_tf32(v.z); v.w = to_tf32(v.w);
        *(float4*)(Qs + row * QSTR + kq) = v;
    }

    // async loaders (64 rows x 32 float4 each)
    auto issueK = [&](int j, float* Kbuf) {
        const float* kp = g_QKV + (size_t)(j * 64) * QKVN + DIM + kvh * HD;
        #pragma unroll
        for (int i = 0; i < 8; i++) {
            int l = tid + i * 256;
            int row = l >> 5, kq = (l & 31) * 4;
            cp_async16(Kbuf + row * QSTR + kq, kp + (size_t)row * QKVN + kq);
        }
        CP_COMMIT();
    };
    auto issueV = [&](int j) {
        const float* vp = g_QKV + (size_t)(j * 64) * QKVN + DIM + KVDIM + kvh * HD;
        #pragma unroll
        for (int i = 0; i < 8; i++) {
            int l = tid + i * 256;
            int row = l >> 5, kq = (l & 31) * 4;
            cp_async16(Vs + row * VSTR + kq, vp + (size_t)row * QKVN + kq);
        }
        CP_COMMIT();
    };

    float oacc[16][4];
    #pragma unroll
    for (int nt = 0; nt < 16; nt++)
        #pragma unroll
        for (int r = 0; r < 4; r++) oacc[nt][r] = 0.f;
    float m0 = -1e30f, m1 = -1e30f, l0 = 0.f, l1 = 0.f;

    int row0 = qbase + wbase + g, row1 = row0 + 8;
    int jmax = 2 * qtile + 1;

    issueK(0, Ks0);   // prologue: K(0) in flight

    for (int j = 0; j <= jmax; j++) {
        int kvbase = j * 64;
        __syncthreads();               // Vs free (prev PV done); Q stores visible
        issueV(j);
        int jn = (j + 1 <= jmax) ? j + 1 : jmax;
        issueK(jn, (j & 1) ? Ks0 : Ks1);   // prefetch next K into other buffer
        CP_WAIT(2);                    // K(j) ready (V(j), K(j+1) may pend)
        __syncthreads();
        const float* Kc = (j & 1) ? Ks1 : Ks0;

        // --- S = Q @ K^T ---
        float sacc[8][4];
        #pragma unroll
        for (int nt = 0; nt < 8; nt++)
            #pragma unroll
            for (int r = 0; r < 4; r++) sacc[nt][r] = 0.f;
        #pragma unroll
        for (int k8 = 0; k8 < 128; k8 += 8) {
            unsigned a[4];
            const float* ap = Qs + (wbase + g) * QSTR + k8 + t;
            a[0] = __float_as_uint(ap[0]);
            a[1] = __float_as_uint(ap[8 * QSTR]);
            a[2] = __float_as_uint(ap[4]);
            a[3] = __float_as_uint(ap[8 * QSTR + 4]);
            #pragma unroll
            for (int nt = 0; nt < 8; nt++) {
                unsigned b[2];
                const float* bp = Kc + (nt * 8 + g) * QSTR + k8 + t;
                b[0] = to_tf32u(bp[0]);
                b[1] = to_tf32u(bp[4]);
                mma_tf32(sacc[nt], a, b);
            }
        }

        // --- scale + causal mask + online softmax (register, quad-shfl) ---
        float mn0 = m0, mn1 = m1;
        #pragma unroll
        for (int nt = 0; nt < 8; nt++) {
            int c0 = kvbase + nt * 8 + 2 * t, c1 = c0 + 1;
            float v0 = (c0 <= row0) ? sacc[nt][0] * scale : -1e30f;
            float v1 = (c1 <= row0) ? sacc[nt][1] * scale : -1e30f;
            float v2 = (c0 <= row1) ? sacc[nt][2] * scale : -1e30f;
            float v3 = (c1 <= row1) ? sacc[nt][3] * scale : -1e30f;
            sacc[nt][0] = v0; sacc[nt][1] = v1; sacc[nt][2] = v2; sacc[nt][3] = v3;
            mn0 = fmaxf(mn0, fmaxf(v0, v1));
            mn1 = fmaxf(mn1, fmaxf(v2, v3));
        }
        mn0 = fmaxf(mn0, __shfl_xor_sync(0xffffffffu, mn0, 1));
        mn0 = fmaxf(mn0, __shfl_xor_sync(0xffffffffu, mn0, 2));
        mn1 = fmaxf(mn1, __shfl_xor_sync(0xffffffffu, mn1, 1));
        mn1 = fmaxf(mn1, __shfl_xor_sync(0xffffffffu, mn1, 2));
        float a0 = exp2f((m0 - mn0) * L2E);
        float a1 = exp2f((m1 - mn1) * L2E);
        m0 = mn0; m1 = mn1;
        float s0 = 0.f, s1 = 0.f;
        float* pr0 = Ps + (wbase + g) * PSTR + 2 * t;
        float* pr1 = pr0 + 8 * PSTR;
        #pragma unroll
        for (int nt = 0; nt < 8; nt++) {
            float p0 = exp2f((sacc[nt][0] - m0) * L2E);
            float p1 = exp2f((sacc[nt][1] - m0) * L2E);
            float p2 = exp2f((sacc[nt][2] - m1) * L2E);
            float p3 = exp2f((sacc[nt][3] - m1) * L2E);
            s0 += p0 + p1; s1 += p2 + p3;
            *(float2*)(pr0 + nt * 8) = make_float2(to_tf32(p0), to_tf32(p1));
            *(float2*)(pr1 + nt * 8) = make_float2(to_tf32(p2), to_tf32(p3));
        }
        s0 += __shfl_xor_sync(0xffffffffu, s0, 1);
        s0 += __shfl_xor_sync(0xffffffffu, s0, 2);
        s1 += __shfl_xor_sync(0xffffffffu, s1, 1);
        s1 += __shfl_xor_sync(0xffffffffu, s1, 2);
        l0 = l0 * a0 + s0;
        l1 = l1 * a1 + s1;
        #pragma unroll
        for (int nt = 0; nt < 16; nt++) {
            oacc[nt][0] *= a0; oacc[nt][1] *= a0;
            oacc[nt][2] *= a1; oacc[nt][3] *= a1;
        }

        CP_WAIT(1);                    // V(j) ready (K(j+1) may pend)
        __syncthreads();

        // --- O += P @ V ---
        #pragma unroll
        for (int k8 = 0; k8 < 64; k8 += 8) {
            unsigned a[4];
            const float* ap = Ps + (wbase + g) * PSTR + k8 + t;
            a[0] = __float_as_uint(ap[0]);
            a[1] = __float_as_uint(ap[8 * PSTR]);
            a[2] = __float_as_uint(ap[4]);
            a[3] = __float_as_uint(ap[8 * PSTR + 4]);
            #pragma unroll
            for (int nt = 0; nt < 16; nt++) {
                unsigned b[2];
                const float* bp = Vs + (k8 + t) * VSTR + nt * 8 + g;
                b[0] = to_tf32u(bp[0]);
                b[1] = to_tf32u(bp[4 * VSTR]);
                mma_tf32(oacc[nt], a, b);
            }
        }
    }

    // --- epilogue: O /= l, write Y ---
    float i0 = 1.f / l0, i1 = 1.f / l1;
    float* y0 = g_Y + (size_t)(qbase + wbase + g) * DIM + h * HD + 2 * t;
    float* y1 = y0 + 8 * DIM;
    #pragma unroll
    for (int nt = 0; nt < 16; nt++) {
        *(float2*)(y0 + nt * 8) = make_float2(oacc[nt][0] * i0, oacc[nt][1] * i0);
        *(float2*)(y1 + nt * 8) = make_float2(oacc[nt][2] * i1, oacc[nt][3] * i1);
    }
}

static const int FLASH_SMEM =
    (128 * QSTR + 2 * 64 * QSTR + 64 * VSTR + 128 * PSTR) * (int)sizeof(float);  // 204800

// ---------------------------------------------------------------------------
// Launch
// ---------------------------------------------------------------------------
extern "C" void kernel_launch(void* const* d_in, const int* in_sizes, int n_in,
                              void* d_out, int out_size)
{
    const float* x    = (const float*)d_in[0];
    const float* wq   = (const float*)d_in[1];
    const float* wk   = (const float*)d_in[2];
    const float* wv   = (const float*)d_in[3];
    const float* wp   = (const float*)d_in[4];
    const float* gain = (const float*)d_in[5];
    float* out = (float*)d_out;

    cudaFuncSetAttribute(flash_kernel,
                         cudaFuncAttributeMaxDynamicSharedMemorySize, FLASH_SMEM);
    cudaFuncSetAttribute(gemm_qkv_kernel,
                         cudaFuncAttributeMaxDynamicSharedMemorySize, GEMM_SMEM);
    cudaFuncSetAttribute(gemm_proj_kernel,
                         cudaFuncAttributeMaxDynamicSharedMemorySize, GEMM_SMEM);

    invf_kernel<<<1, 64>>>();
    rope_table_kernel<<<(SEQ * (HD/2) + 255) / 256, 256>>>();
    quantize_kernel<<<NROWS_W, 256>>>(wq, wk, wv, wp);
    gemm_qkv_kernel<<<dim3(QKVN / 128, SEQ / 128), 256, GEMM_SMEM>>>(x);
    qk_post_kernel<<<(SEQ * (NH + NKV) + 7) / 8, 256>>>(gain);
    flash_kernel<<<dim3(SEQ / 128, NH), 256, FLASH_SMEM>>>();
    gemm_proj_kernel<<<dim3(DIM / 128, SEQ / 128), 256, GEMM_SMEM>>>(out);
}

// round 11
// speedup vs baseline: 6.1112x; 1.5340x over previous
#include <cuda_runtime.h>
#include <cuda_fp16.h>
#include <math.h>

// ---------------------------------------------------------------------------
// Problem constants
// ---------------------------------------------------------------------------
#define SEQ      4096
#define DIM      2048
#define NH       16
#define NKV      4
#define HD       128
#define KVDIM    (NKV*HD)          // 512
#define QKVN     (DIM + 2*KVDIM)   // 3072
#define NROWS_W  (QKVN + DIM)      // 5120 quantize rows

// ---------------------------------------------------------------------------
// Device-global scratch (no cudaMalloc allowed)
// ---------------------------------------------------------------------------
__device__ __half  g_Wqkv[QKVN * DIM];   // TERNARY {-1,0,1} fp16 [3072][2048]
__device__ __half  g_Wp  [DIM  * DIM];   // TERNARY fp16 [2048][2048]
__device__ float   g_sqkv[QKVN];         // per-row scales
__device__ float   g_sp  [DIM];
__device__ __half  g_x_h [SEQ * DIM];    // x in fp16
__device__ float   g_QKV [SEQ * QKVN];   // qkv output f32 (for rmsnorm precision)
__device__ __half  g_QKVh[SEQ * QKVN];   // qkv fp16 (q/k overwritten post-rope)
__device__ __half  g_Yh  [SEQ * DIM];    // attention output fp16
__device__ float   g_cos [SEQ * (HD/2)];
__device__ float   g_sin [SEQ * (HD/2)];
__device__ double  g_invf[HD/2];

// ---------------------------------------------------------------------------
// helpers
// ---------------------------------------------------------------------------
__device__ __forceinline__ void mma_f16(float d[4], const unsigned a[4], const unsigned b[2]) {
    asm volatile(
        "mma.sync.aligned.m16n8k16.row.col.f32.f16.f16.f32 "
        "{%0,%1,%2,%3},{%4,%5,%6,%7},{%8,%9},{%0,%1,%2,%3};"
        : "+f"(d[0]), "+f"(d[1]), "+f"(d[2]), "+f"(d[3])
        : "r"(a[0]), "r"(a[1]), "r"(a[2]), "r"(a[3]), "r"(b[0]), "r"(b[1]));
}

__device__ __forceinline__ void cp_async16(__half* smem_dst, const __half* gmem_src) {
    unsigned s = (unsigned)__cvta_generic_to_shared(smem_dst);
    asm volatile("cp.async.cg.shared.global [%0], [%1], 16;" :: "r"(s), "l"(gmem_src));
}
#define CP_COMMIT()  asm volatile("cp.async.commit_group;")
#define CP_WAIT(N)   asm volatile("cp.async.wait_group %0;" :: "n"(N))

__device__ __forceinline__ unsigned pack2(__half lo, __half hi) {
    __half2 h = __halves2half2(lo, hi);
    return *(unsigned*)&h;
}

// ---------------------------------------------------------------------------
// 1) RoPE tables: fp64 invf + fp64 range reduction + fast fp32 sincos.
// ---------------------------------------------------------------------------
__global__ void invf_kernel() {
    int j = threadIdx.x;
    if (j < HD/2) g_invf[j] = pow(10000.0, -(double)j / 64.0);
}

__global__ void rope_table_kernel() {
    int idx = blockIdx.x * blockDim.x + threadIdx.x;
    if (idx >= SEQ * (HD/2)) return;
    int t = idx >> 6;
    int j = idx & 63;
    double ang = (double)t * g_invf[j];
    double q   = rint(ang * 0.15915494309189535);
    float  r   = (float)(ang - q * 6.283185307179586476);
    float sn, cn;
    __sincosf(r, &sn, &cn);
    g_cos[idx] = cn;
    g_sin[idx] = sn;
}

// ---------------------------------------------------------------------------
// 2) x -> fp16
// ---------------------------------------------------------------------------
__global__ __launch_bounds__(256) void xh_kernel(const float* __restrict__ x) {
    int i = (blockIdx.x * 256 + threadIdx.x) * 4;
    float4 v = *(const float4*)(x + i);
    *(__half2*)(g_x_h + i)     = __floats2half2_rn(v.x, v.y);
    *(__half2*)(g_x_h + i + 2) = __floats2half2_rn(v.z, v.w);
}

// ---------------------------------------------------------------------------
// 3) BitLinear quantize -> TERNARY fp16 weights + per-row scale.
// ---------------------------------------------------------------------------
__global__ __launch_bounds__(256) void quantize_kernel(
    const float* __restrict__ wq, const float* __restrict__ wk,
    const float* __restrict__ wv, const float* __restrict__ wp)
{
    int row = blockIdx.x;
    const float* src; __half* dst; float* sdst;
    if      (row < DIM)        { src = wq + (size_t)row * DIM;                 dst = g_Wqkv + (size_t)row * DIM; sdst = g_sqkv + row; }
    else if (row < DIM + KVDIM){ src = wk + (size_t)(row - DIM) * DIM;         dst = g_Wqkv + (size_t)row * DIM; sdst = g_sqkv + row; }
    else if (row < QKVN)       { src = wv + (size_t)(row - DIM - KVDIM) * DIM; dst = g_Wqkv + (size_t)row * DIM; sdst = g_sqkv + row; }
    else                       { src = wp + (size_t)(row - QKVN) * DIM;        dst = g_Wp + (size_t)(row - QKVN) * DIM; sdst = g_sp + (row - QKVN); }

    __shared__ double red[256];
    double acc = 0.0;
    for (int k = threadIdx.x; k < DIM; k += 256) acc += (double)fabsf(src[k]);
    red[threadIdx.x] = acc;
    __syncthreads();
    for (int off = 128; off > 0; off >>= 1) {
        if (threadIdx.x < off) red[threadIdx.x] += red[threadIdx.x + off];
        __syncthreads();
    }
    float s = fmaxf((float)(red[0] / (double)DIM), 1e-5f);
    if (threadIdx.x == 0) *sdst = s;
    for (int k = threadIdx.x; k < DIM; k += 256) {
        float w = rintf(src[k] / s);
        w = fminf(fmaxf(w, -1.f), 1.f);
        dst[k] = __float2half_rn(w);   // -1/0/1 exact
    }
}

// ---------------------------------------------------------------------------
// 4) FP16 GEMM, cp.async double-buffered: C[M,N] = (A @ T^T) * s[n]
//    BM=BN=128, BK=64, 256 threads = 8 warps (4x2), warp tile 32x64.
//    Smem stride 88 halves (16B-aligned rows, conflict-free fragments).
// ---------------------------------------------------------------------------
#define GSTR 88
#define GSTG (128 * GSTR)    // halves per stage per operand

__device__ __forceinline__ void gemm_core(
    const __half* __restrict__ A, const __half* __restrict__ B,
    const float* __restrict__ sc, float* __restrict__ C,
    __half* __restrict__ Ch, int N)
{
    extern __shared__ __half smh[];
    __half* As = smh;               // [2][128*88]
    __half* Bs = smh + 2 * GSTG;    // [2][128*88]
    const int K = DIM;
    int tid = threadIdx.x, warp = tid >> 5, lane = tid & 31;
    int g = lane >> 2, t = lane & 3;
    int wm = (warp & 3) * 32, wn = (warp >> 2) * 64;
    const __half* Ab = A + (size_t)blockIdx.y * 128 * K;
    const __half* Bb = B + (size_t)blockIdx.x * 128 * K;

    float acc[2][8][4];
    #pragma unroll
    for (int mt = 0; mt < 2; mt++)
        #pragma unroll
        for (int nt = 0; nt < 8; nt++)
            #pragma unroll
            for (int r = 0; r < 4; r++) acc[mt][nt][r] = 0.f;

    // stage loader: 128 rows x 8 chunks of 8 halves (16B) per operand
    auto load_stage = [&](int stage, int k0) {
        __half* Ad = As + stage * GSTG;
        __half* Bd = Bs + stage * GSTG;
        #pragma unroll
        for (int i = 0; i < 4; i++) {
            int l = tid + i * 256;
            int row = l >> 3, c8 = (l & 7) * 8;
            cp_async16(Ad + row * GSTR + c8, Ab + (size_t)row * K + k0 + c8);
            cp_async16(Bd + row * GSTR + c8, Bb + (size_t)row * K + k0 + c8);
        }
        CP_COMMIT();
    };

    load_stage(0, 0);
    const int nIter = K / 64;   // 32
    for (int it = 0; it < nIter; it++) {
        CP_WAIT(0);
        __syncthreads();
        if (it + 1 < nIter) load_stage((it + 1) & 1, (it + 1) * 64);

        const __half* Ac = As + (it & 1) * GSTG;
        const __half* Bc = Bs + (it & 1) * GSTG;
        #pragma unroll
        for (int kk = 0; kk < 64; kk += 16) {
            unsigned a[2][4];
            #pragma unroll
            for (int mt = 0; mt < 2; mt++) {
                const __half* ap = Ac + (wm + mt * 16 + g) * GSTR + kk + 2 * t;
                a[mt][0] = *(const unsigned*)(ap);
                a[mt][1] = *(const unsigned*)(ap + 8 * GSTR);
                a[mt][2] = *(const unsigned*)(ap + 8);
                a[mt][3] = *(const unsigned*)(ap + 8 * GSTR + 8);
            }
            #pragma unroll
            for (int nt = 0; nt < 8; nt++) {
                const __half* bp = Bc + (wn + nt * 8 + g) * GSTR + kk + 2 * t;
                unsigned b[2];
                b[0] = *(const unsigned*)(bp);
                b[1] = *(const unsigned*)(bp + 8);
                mma_f16(acc[0][nt], a[0], b);
                mma_f16(acc[1][nt], a[1], b);
            }
        }
        __syncthreads();
    }

    int brow = blockIdx.y * 128, bcol = blockIdx.x * 128;
    #pragma unroll
    for (int mt = 0; mt < 2; mt++) {
        int r0 = brow + wm + mt * 16 + g;
        #pragma unroll
        for (int nt = 0; nt < 8; nt++) {
            int c = bcol + wn + nt * 8 + 2 * t;
            float s0 = sc[c], s1 = sc[c + 1];
            float v00 = acc[mt][nt][0] * s0, v01 = acc[mt][nt][1] * s1;
            float v10 = acc[mt][nt][2] * s0, v11 = acc[mt][nt][3] * s1;
            *(float2*)(C + (size_t)r0 * N + c)       = make_float2(v00, v01);
            *(float2*)(C + (size_t)(r0 + 8) * N + c) = make_float2(v10, v11);
            if (Ch) {
                *(__half2*)(Ch + (size_t)r0 * N + c)       = __floats2half2_rn(v00, v01);
                *(__half2*)(Ch + (size_t)(r0 + 8) * N + c) = __floats2half2_rn(v10, v11);
            }
        }
    }
}

__global__ __launch_bounds__(256, 2) void gemm_qkv_kernel() {
    gemm_core(g_x_h, g_Wqkv, g_sqkv, g_QKV, g_QKVh, QKVN);
}
__global__ __launch_bounds__(256, 2) void gemm_proj_kernel(float* __restrict__ out) {
    gemm_core(g_Yh, g_Wp, g_sp, out, (__half*)0, DIM);
}
static const int GEMM_SMEM = 4 * GSTG * (int)sizeof(__half);  // 90112

// ---------------------------------------------------------------------------
// 5) Q/K post: RMSNorm (eps=2^-23) -> RoPE -> gain; f32 in, fp16 out.
// ---------------------------------------------------------------------------
__global__ __launch_bounds__(256) void qk_post_kernel(const float* __restrict__ gain) {
    int widx = blockIdx.x * 8 + (threadIdx.x >> 5);
    int lane = threadIdx.x & 31;
    if (widx >= SEQ * (NH + NKV)) return;
    int pos  = widx / (NH + NKV);
    int slot = widx - pos * (NH + NKV);

    size_t off; float gv = 1.f;
    if (slot < NH) { off = (size_t)pos * QKVN + slot * HD; gv = gain[slot]; }
    else           { off = (size_t)pos * QKVN + DIM + (slot - NH) * HD; }
    const float* p = g_QKV + off;
    __half* ph = g_QKVh + off;

    float v0 = p[lane], v1 = p[lane+32], v2 = p[lane+64], v3 = p[lane+96];
    float ss = v0*v0 + v1*v1 + v2*v2 + v3*v3;
    #pragma unroll
    for (int o = 16; o > 0; o >>= 1) ss += __shfl_xor_sync(0xffffffffu, ss, o);
    float ms = ss * (1.f / 128.f) + 1.1920928955078125e-07f;
    float r  = rsqrtf(ms);
    r = r * (1.5f - 0.5f * ms * r * r);
    v0 *= r; v1 *= r; v2 *= r; v3 *= r;

    const float* cr = g_cos + pos * 64;
    const float* sr = g_sin + pos * 64;
    float c0 = cr[lane], s0 = sr[lane], c1 = cr[lane+32], s1 = sr[lane+32];
    float o0 =  v0 * c0 + v2 * s0;
    float o2 = -v0 * s0 + v2 * c0;
    float o1 =  v1 * c1 + v3 * s1;
    float o3 = -v1 * s1 + v3 * c1;
    ph[lane]    = __float2half_rn(o0 * gv);
    ph[lane+32] = __float2half_rn(o1 * gv);
    ph[lane+64] = __float2half_rn(o2 * gv);
    ph[lane+96] = __float2half_rn(o3 * gv);
}

// ---------------------------------------------------------------------------
// 6) FP16 flash attention, cp.async pipelined, 2 blocks/SM target.
//    Block = (128 q-rows, head). K double-buffered; V async over softmax.
//    Smem (halves): Qs[128][136] + Ks[2][64][136] + Vs[64][136] + Ps[128][72]
//    = 105472 B -> 2 blocks/SM.
// ---------------------------------------------------------------------------
#define FSTR 136
#define PSTR 72

__global__ __launch_bounds__(256, 2) void flash_kernel() {
    extern __shared__ __half smf[];
    __half* Qs  = smf;                    // [128][136]
    __half* Ks0 = Qs  + 128 * FSTR;       // [64][136]
    __half* Ks1 = Ks0 + 64 * FSTR;        // [64][136]
    __half* Vs  = Ks1 + 64 * FSTR;        // [64][136]
    __half* Ps  = Vs  + 64 * FSTR;        // [128][72]

    int qtile = gridDim.x - 1 - blockIdx.x;   // longest first
    int h = blockIdx.y, kvh = h >> 2;
    int qbase = qtile * 128;
    int tid = threadIdx.x, warp = tid >> 5, lane = tid & 31;
    int g = lane >> 2, t = lane & 3;
    int wbase = warp * 16;
    const float scale = 0.08838834764831845f;
    const float L2E = 1.4426950408889634f;

    // Load Q tile: 128 rows x 16 chunks(8h)
    const __half* qp = g_QKVh + (size_t)qbase * QKVN + h * HD;
    #pragma unroll
    for (int i = 0; i < 8; i++) {
        int l = tid + i * 256;
        int row = l >> 4, c8 = (l & 15) * 8;
        cp_async16(Qs + row * FSTR + c8, qp + (size_t)row * QKVN + c8);
    }
    CP_COMMIT();

    auto issueK = [&](int j, __half* Kbuf) {
        const __half* kp = g_QKVh + (size_t)(j * 64) * QKVN + DIM + kvh * HD;
        #pragma unroll
        for (int i = 0; i < 4; i++) {
            int l = tid + i * 256;
            int row = l >> 4, c8 = (l & 15) * 8;
            cp_async16(Kbuf + row * FSTR + c8, kp + (size_t)row * QKVN + c8);
        }
        CP_COMMIT();
    };
    auto issueV = [&](int j) {
        const __half* vp = g_QKVh + (size_t)(j * 64) * QKVN + DIM + KVDIM + kvh * HD;
        #pragma unroll
        for (int i = 0; i < 4; i++) {
            int l = tid + i * 256;
            int row = l >> 4, c8 = (l & 15) * 8;
            cp_async16(Vs + row * FSTR + c8, vp + (size_t)row * QKVN + c8);
        }
        CP_COMMIT();
    };

    float oacc[16][4];
    #pragma unroll
    for (int nt = 0; nt < 16; nt++)
        #pragma unroll
        for (int r = 0; r < 4; r++) oacc[nt][r] = 0.f;
    float m0 = -1e30f, m1 = -1e30f, l0 = 0.f, l1 = 0.f;

    int row0 = qbase + wbase + g, row1 = row0 + 8;
    int jmax = 2 * qtile + 1;

    issueK(0, Ks0);   // groups in flight: [Q, K0]

    for (int j = 0; j <= jmax; j++) {
        int kvbase = j * 64;
        __syncthreads();               // Vs free (prev PV done)
        issueV(j);
        int jn = (j + 1 <= jmax) ? j + 1 : jmax;
        issueK(jn, (j & 1) ? Ks0 : Ks1);
        CP_WAIT(2);                    // Q(+K(j)) ready; V(j), K(j+1) may pend
        __syncthreads();
        const __half* Kc = (j & 1) ? Ks1 : Ks0;

        // --- S = Q @ K^T ---
        float sacc[8][4];
        #pragma unroll
        for (int nt = 0; nt < 8; nt++)
            #pragma unroll
            for (int r = 0; r < 4; r++) sacc[nt][r] = 0.f;
        #pragma unroll
        for (int kk = 0; kk < 128; kk += 16) {
            unsigned a[4];
            const __half* ap = Qs + (wbase + g) * FSTR + kk + 2 * t;
            a[0] = *(const unsigned*)(ap);
            a[1] = *(const unsigned*)(ap + 8 * FSTR);
            a[2] = *(const unsigned*)(ap + 8);
            a[3] = *(const unsigned*)(ap + 8 * FSTR + 8);
            #pragma unroll
            for (int nt = 0; nt < 8; nt++) {
                const __half* bp = Kc + (nt * 8 + g) * FSTR + kk + 2 * t;
                unsigned b[2];
                b[0] = *(const unsigned*)(bp);
                b[1] = *(const unsigned*)(bp + 8);
                mma_f16(sacc[nt], a, b);
            }
        }

        // --- scale + causal mask + online softmax ---
        float mn0 = m0, mn1 = m1;
        #pragma unroll
        for (int nt = 0; nt < 8; nt++) {
            int c0 = kvbase + nt * 8 + 2 * t, c1 = c0 + 1;
            float v0 = (c0 <= row0) ? sacc[nt][0] * scale : -1e30f;
            float v1 = (c1 <= row0) ? sacc[nt][1] * scale : -1e30f;
            float v2 = (c0 <= row1) ? sacc[nt][2] * scale : -1e30f;
            float v3 = (c1 <= row1) ? sacc[nt][3] * scale : -1e30f;
            sacc[nt][0] = v0; sacc[nt][1] = v1; sacc[nt][2] = v2; sacc[nt][3] = v3;
            mn0 = fmaxf(mn0, fmaxf(v0, v1));
            mn1 = fmaxf(mn1, fmaxf(v2, v3));
        }
        mn0 = fmaxf(mn0, __shfl_xor_sync(0xffffffffu, mn0, 1));
        mn0 = fmaxf(mn0, __shfl_xor_sync(0xffffffffu, mn0, 2));
        mn1 = fmaxf(mn1, __shfl_xor_sync(0xffffffffu, mn1, 1));
        mn1 = fmaxf(mn1, __shfl_xor_sync(0xffffffffu, mn1, 2));
        float a0 = exp2f((m0 - mn0) * L2E);
        float a1 = exp2f((m1 - mn1) * L2E);
        m0 = mn0; m1 = mn1;
        float s0 = 0.f, s1 = 0.f;
        __half* pr0 = Ps + (wbase + g) * PSTR + 2 * t;
        __half* pr1 = pr0 + 8 * PSTR;
        #pragma unroll
        for (int nt = 0; nt < 8; nt++) {
            float p0 = exp2f((sacc[nt][0] - m0) * L2E);
            float p1 = exp2f((sacc[nt][1] - m0) * L2E);
            float p2 = exp2f((sacc[nt][2] - m1) * L2E);
            float p3 = exp2f((sacc[nt][3] - m1) * L2E);
            s0 += p0 + p1; s1 += p2 + p3;
            *(__half2*)(pr0 + nt * 8) = __floats2half2_rn(p0, p1);
            *(__half2*)(pr1 + nt * 8) = __floats2half2_rn(p2, p3);
        }
        s0 += __shfl_xor_sync(0xffffffffu, s0, 1);
        s0 += __shfl_xor_sync(0xffffffffu, s0, 2);
        s1 += __shfl_xor_sync(0xffffffffu, s1, 1);
        s1 += __shfl_xor_sync(0xffffffffu, s1, 2);
        l0 = l0 * a0 + s0;
        l1 = l1 * a1 + s1;
        #pragma unroll
        for (int nt = 0; nt < 16; nt++) {
            oacc[nt][0] *= a0; oacc[nt][1] *= a0;
            oacc[nt][2] *= a1; oacc[nt][3] *= a1;
        }

        CP_WAIT(1);                    // V(j) ready (K(j+1) may pend)
        __syncthreads();

        // --- O += P @ V ---
        #pragma unroll
        for (int kk = 0; kk < 64; kk += 16) {
            unsigned a[4];
            const __half* ap = Ps + (wbase + g) * PSTR + kk + 2 * t;
            a[0] = *(const unsigned*)(ap);
            a[1] = *(const unsigned*)(ap + 8 * PSTR);
            a[2] = *(const unsigned*)(ap + 8);
            a[3] = *(const unsigned*)(ap + 8 * PSTR + 8);
            #pragma unroll
            for (int nt = 0; nt < 16; nt++) {
                int col = nt * 8 + g;
                const __half* vb = Vs + (kk + 2 * t) * FSTR + col;
                unsigned b[2];
                b[0] = pack2(vb[0],        vb[FSTR]);
                b[1] = pack2(vb[8 * FSTR], vb[9 * FSTR]);
                mma_f16(oacc[nt], a, b);
            }
        }
    }

    // --- epilogue: O /= l, write Yh (fp16) ---
    float i0 = 1.f / l0, i1 = 1.f / l1;
    __half* y0 = g_Yh + (size_t)(qbase + wbase + g) * DIM + h * HD + 2 * t;
    __half* y1 = y0 + 8 * DIM;
    #pragma unroll
    for (int nt = 0; nt < 16; nt++) {
        *(__half2*)(y0 + nt * 8) = __floats2half2_rn(oacc[nt][0] * i0, oacc[nt][1] * i0);
        *(__half2*)(y1 + nt * 8) = __floats2half2_rn(oacc[nt][2] * i1, oacc[nt][3] * i1);
    }
}

static const int FLASH_SMEM =
    (128 * FSTR + 2 * 64 * FSTR + 64 * FSTR + 128 * PSTR) * (int)sizeof(__half);  // 105472

// ---------------------------------------------------------------------------
// Launch
// ---------------------------------------------------------------------------
extern "C" void kernel_launch(void* const* d_in, const int* in_sizes, int n_in,
                              void* d_out, int out_size)
{
    const float* x    = (const float*)d_in[0];
    const float* wq   = (const float*)d_in[1];
    const float* wk   = (const float*)d_in[2];
    const float* wv   = (const float*)d_in[3];
    const float* wp   = (const float*)d_in[4];
    const float* gain = (const float*)d_in[5];
    float* out = (float*)d_out;

    cudaFuncSetAttribute(flash_kernel,
                         cudaFuncAttributeMaxDynamicSharedMemorySize, FLASH_SMEM);
    cudaFuncSetAttribute(gemm_qkv_kernel,
                         cudaFuncAttributeMaxDynamicSharedMemorySize, GEMM_SMEM);
    cudaFuncSetAttribute(gemm_proj_kernel,
                         cudaFuncAttributeMaxDynamicSharedMemorySize, GEMM_SMEM);

    invf_kernel<<<1, 64>>>();
    rope_table_kernel<<<(SEQ * (HD/2) + 255) / 256, 256>>>();
    xh_kernel<<<SEQ * DIM / 1024, 256>>>(x);
    quantize_kernel<<<NROWS_W, 256>>>(wq, wk, wv, wp);
    gemm_qkv_kernel<<<dim3(QKVN / 128, SEQ / 128), 256, GEMM_SMEM>>>();
    qk_post_kernel<<<(SEQ * (NH + NKV) + 7) / 8, 256>>>(gain);
    flash_kernel<<<dim3(SEQ / 128, NH), 256, FLASH_SMEM>>>();
    gemm_proj_kernel<<<dim3(DIM / 128, SEQ / 128), 256, GEMM_SMEM>>>(out);
}